// round 1
// baseline (speedup 1.0000x reference)
#include <cuda_runtime.h>
#include <math.h>

#define Bdim 4
#define Nseq 2048
#define DIM 1024
#define NH 16
#define HD 64
#define SCALE 0.125f   // 1/sqrt(64)

// Scratch: [B*H, N, HD] for each of q, k, v  (q pre-scaled)
__device__ float g_q[Bdim * NH * Nseq * HD];
__device__ float g_k[Bdim * NH * Nseq * HD];
__device__ float g_v[Bdim * NH * Nseq * HD];

// ---------------------------------------------------------------------------
// QKV GEMM: out[m, n] = sum_k x[m,k] * w[n,k] + bias[n]
// M = B*N = 8192, Ncols = 3*DIM = 3072, K = DIM = 1024.
// Epilogue scatters into g_q/g_k/g_v with [BH, N, HD] layout, scaling Q.
// Tile 64x64x16, 256 threads, 4x4 per thread.
// ---------------------------------------------------------------------------
__global__ __launch_bounds__(256) void qkv_gemm(const float* __restrict__ x,
                                                const float* __restrict__ w,
                                                const float* __restrict__ bias) {
    __shared__ float As[16][64];   // As[k][m]
    __shared__ float Bs[16][64];   // Bs[k][n]

    const int tid = threadIdx.x;
    const int tx = tid & 15;
    const int ty = tid >> 4;
    const int m0 = blockIdx.x * 64;
    const int n0 = blockIdx.y * 64;

    const int lr = tid >> 2;          // 0..63  row within tile
    const int lc = (tid & 3) << 2;    // 0,4,8,12 col within BK

    const float* ag = x + (size_t)(m0 + lr) * DIM + lc;
    const float* bg = w + (size_t)(n0 + lr) * DIM + lc;

    float acc[4][4] = {};

    for (int k0 = 0; k0 < DIM; k0 += 16) {
        float4 av = *(const float4*)(ag + k0);
        float4 bv = *(const float4*)(bg + k0);
        As[lc + 0][lr] = av.x;
        As[lc + 1][lr] = av.y;
        As[lc + 2][lr] = av.z;
        As[lc + 3][lr] = av.w;
        Bs[lc + 0][lr] = bv.x;
        Bs[lc + 1][lr] = bv.y;
        Bs[lc + 2][lr] = bv.z;
        Bs[lc + 3][lr] = bv.w;
        __syncthreads();
#pragma unroll
        for (int kk = 0; kk < 16; kk++) {
            float a[4], b[4];
#pragma unroll
            for (int i = 0; i < 4; i++) a[i] = As[kk][ty * 4 + i];
#pragma unroll
            for (int j = 0; j < 4; j++) b[j] = Bs[kk][tx * 4 + j];
#pragma unroll
            for (int i = 0; i < 4; i++)
#pragma unroll
                for (int j = 0; j < 4; j++)
                    acc[i][j] = fmaf(a[i], b[j], acc[i][j]);
        }
        __syncthreads();
    }

    // Epilogue: n0 is 64-aligned -> whole tile lands in one (seg, head).
    const int seg = n0 / DIM;            // 0=q, 1=k, 2=v
    const int d0 = n0 % DIM;
    const int h = d0 / HD;
    const int bb = m0 / Nseq;            // batch (64 | 2048, so constant per tile)
    const int nrow0 = (m0 % Nseq) + ty * 4;

    float* dst = (seg == 0) ? g_q : (seg == 1) ? g_k : g_v;
    const float sc = (seg == 0) ? SCALE : 1.0f;
    float4 b4 = *(const float4*)&bias[n0 + tx * 4];

#pragma unroll
    for (int i = 0; i < 4; i++) {
        float4 v;
        v.x = (acc[i][0] + b4.x) * sc;
        v.y = (acc[i][1] + b4.y) * sc;
        v.z = (acc[i][2] + b4.z) * sc;
        v.w = (acc[i][3] + b4.w) * sc;
        size_t off = (((size_t)(bb * NH + h) * Nseq) + nrow0 + i) * HD + tx * 4;
        *(float4*)&dst[off] = v;
    }
}

// ---------------------------------------------------------------------------
// Flash attention: one (b,h, 64-query tile) per CTA. 256 threads.
// smem: Qt[64][65] (Qt[kk][r]), Kt[64][65], Vs[64][64], Ps[64][64]
// ---------------------------------------------------------------------------
#define QT_PITCH 65
#define ATTN_SMEM_FLOATS (64 * QT_PITCH * 2 + 64 * 64 * 2)
#define ATTN_SMEM_BYTES (ATTN_SMEM_FLOATS * 4)

__global__ __launch_bounds__(256) void attn_kernel(float* __restrict__ out) {
    extern __shared__ float sm[];
    float* Qt = sm;                         // [64][65], Qt[kk*65 + r]
    float* Kt = sm + 64 * QT_PITCH;         // [64][65], Kt[kk*65 + c]
    float* Vs = Kt + 64 * QT_PITCH;         // [64][64], Vs[jj*64 + hd]
    float* Ps = Vs + 64 * 64;               // [64][64], Ps[r*64 + jj]

    const int bh = blockIdx.x;              // 0..63
    const int q0 = blockIdx.y * 64;
    const float* Qg = g_q + (size_t)bh * Nseq * HD;
    const float* Kg = g_k + (size_t)bh * Nseq * HD;
    const float* Vg = g_v + (size_t)bh * Nseq * HD;

    const int tid = threadIdx.x;
    const int tx = tid & 15;
    const int ty = tid >> 4;

    // Load Q tile transposed
    for (int i = tid; i < 4096; i += 256) {
        int r = i >> 6, c = i & 63;
        Qt[c * QT_PITCH + r] = Qg[(size_t)(q0 + r) * HD + c];
    }

    float m_i[4], l_i[4], o[4][4];
#pragma unroll
    for (int i = 0; i < 4; i++) {
        m_i[i] = -INFINITY;
        l_i[i] = 0.f;
#pragma unroll
        for (int j = 0; j < 4; j++) o[i][j] = 0.f;
    }

    for (int t = 0; t < Nseq; t += 64) {
        // Load K (transposed) and V tiles
        for (int i = tid; i < 4096; i += 256) {
            int r = i >> 6, c = i & 63;
            Kt[c * QT_PITCH + r] = Kg[(size_t)(t + r) * HD + c];
            Vs[i] = Vg[(size_t)(t + r) * HD + c];
        }
        __syncthreads();

        // S = Q K^T (Q pre-scaled)
        float s[4][4] = {};
#pragma unroll 8
        for (int kk = 0; kk < 64; kk++) {
            float a[4], b[4];
#pragma unroll
            for (int i = 0; i < 4; i++) a[i] = Qt[kk * QT_PITCH + ty * 4 + i];
#pragma unroll
            for (int j = 0; j < 4; j++) b[j] = Kt[kk * QT_PITCH + tx * 4 + j];
#pragma unroll
            for (int i = 0; i < 4; i++)
#pragma unroll
                for (int j = 0; j < 4; j++)
                    s[i][j] = fmaf(a[i], b[j], s[i][j]);
        }

        // Online softmax. Row-group = 16 threads (same ty) = aligned half-warp.
#pragma unroll
        for (int i = 0; i < 4; i++) {
            float rm = fmaxf(fmaxf(s[i][0], s[i][1]), fmaxf(s[i][2], s[i][3]));
            rm = fmaxf(rm, __shfl_xor_sync(0xffffffffu, rm, 1));
            rm = fmaxf(rm, __shfl_xor_sync(0xffffffffu, rm, 2));
            rm = fmaxf(rm, __shfl_xor_sync(0xffffffffu, rm, 4));
            rm = fmaxf(rm, __shfl_xor_sync(0xffffffffu, rm, 8));
            float nm = fmaxf(m_i[i], rm);
            float alpha = __expf(m_i[i] - nm);
            m_i[i] = nm;
            float rs = 0.f;
#pragma unroll
            for (int j = 0; j < 4; j++) {
                s[i][j] = __expf(s[i][j] - nm);
                rs += s[i][j];
            }
            rs += __shfl_xor_sync(0xffffffffu, rs, 1);
            rs += __shfl_xor_sync(0xffffffffu, rs, 2);
            rs += __shfl_xor_sync(0xffffffffu, rs, 4);
            rs += __shfl_xor_sync(0xffffffffu, rs, 8);
            l_i[i] = l_i[i] * alpha + rs;
#pragma unroll
            for (int j = 0; j < 4; j++) o[i][j] *= alpha;
        }

        // Write P tile
#pragma unroll
        for (int i = 0; i < 4; i++) {
            float4 p4 = make_float4(s[i][0], s[i][1], s[i][2], s[i][3]);
            *(float4*)&Ps[(ty * 4 + i) * 64 + tx * 4] = p4;
        }
        __syncthreads();

        // O += P V
#pragma unroll 8
        for (int jj = 0; jj < 64; jj++) {
            float a[4], b[4];
#pragma unroll
            for (int i = 0; i < 4; i++) a[i] = Ps[(ty * 4 + i) * 64 + jj];
#pragma unroll
            for (int j = 0; j < 4; j++) b[j] = Vs[jj * 64 + tx * 4 + j];
#pragma unroll
            for (int i = 0; i < 4; i++)
#pragma unroll
                for (int j = 0; j < 4; j++)
                    o[i][j] = fmaf(a[i], b[j], o[i][j]);
        }
        __syncthreads();
    }

    // Final write: out[b, q, h*64 + hd]
    const int bb = bh >> 4;
    const int h = bh & 15;
#pragma unroll
    for (int i = 0; i < 4; i++) {
        float inv = 1.0f / l_i[i];
        int q = q0 + ty * 4 + i;
        float4 v = make_float4(o[i][0] * inv, o[i][1] * inv,
                               o[i][2] * inv, o[i][3] * inv);
        *(float4*)&out[((size_t)(bb * Nseq + q)) * DIM + h * HD + tx * 4] = v;
    }
}

extern "C" void kernel_launch(void* const* d_in, const int* in_sizes, int n_in,
                              void* d_out, int out_size) {
    const float* x = (const float*)d_in[0];
    const float* w = (const float*)d_in[1];
    const float* bias = (const float*)d_in[2];
    float* out = (float*)d_out;

    cudaFuncSetAttribute(attn_kernel,
                         cudaFuncAttributeMaxDynamicSharedMemorySize,
                         ATTN_SMEM_BYTES);

    dim3 ggrid(Bdim * Nseq / 64, 3 * DIM / 64);   // (128, 48)
    qkv_gemm<<<ggrid, 256>>>(x, w, bias);

    dim3 agrid(Bdim * NH, Nseq / 64);             // (64, 32)
    attn_kernel<<<agrid, 256, ATTN_SMEM_BYTES>>>(out);
}

// round 8
// speedup vs baseline: 2.4651x; 2.4651x over previous
#include <cuda_runtime.h>
#include <math.h>
#include <cstdint>

#define Bdim 4
#define Nseq 2048
#define DIM 1024
#define NH 16
#define HD 64
#define SCALE 0.125f   // 1/sqrt(64)

// Scratch: [B*H, N, HD] for q, k, v. Values pre-rounded to tf32 (q pre-scaled).
__device__ float g_q[Bdim * NH * Nseq * HD];
__device__ float g_k[Bdim * NH * Nseq * HD];
__device__ float g_v[Bdim * NH * Nseq * HD];

__device__ __forceinline__ uint32_t f2tf32(float f) {
    uint32_t r;
    asm("cvt.rna.tf32.f32 %0, %1;" : "=r"(r) : "f"(f));
    return r;
}

// m16n8k8 tf32 mma. c += a * b.
__device__ __forceinline__ void mma8(float* c, uint32_t a0, uint32_t a1,
                                     uint32_t a2, uint32_t a3,
                                     uint32_t b0, uint32_t b1) {
    asm volatile(
        "mma.sync.aligned.m16n8k8.row.col.f32.tf32.tf32.f32 "
        "{%0,%1,%2,%3},{%4,%5,%6,%7},{%8,%9},{%0,%1,%2,%3};"
        : "+f"(c[0]), "+f"(c[1]), "+f"(c[2]), "+f"(c[3])
        : "r"(a0), "r"(a1), "r"(a2), "r"(a3), "r"(b0), "r"(b1));
}

// Permute k within each 8-group so (k, k+4) become adjacent floats:
// pos = group*8 + (k%4)*2 + ((k/4)%2)
__device__ __forceinline__ int perm8(int k) {
    return (k & ~7) + ((k & 3) << 1) + ((k >> 2) & 1);
}

// ---------------------------------------------------------------------------
// QKV GEMM: C[m,n] = sum_k x[m,k]*w[n,k] + bias[n]. M=8192 N=3072 K=1024.
// CTA 128x128, k-chunk 32, double-buffered smem, tf32 mma.sync.
// ---------------------------------------------------------------------------
#define GP 36                       // smem row pitch (floats)
#define GEMM_SMEM (4 * 128 * GP * 4)   // 2 bufs x (A+B) = 73728 B

__global__ __launch_bounds__(256) void qkv_gemm_mma(const float* __restrict__ x,
                                                    const float* __restrict__ w,
                                                    const float* __restrict__ bias) {
    extern __shared__ float sm[];
    float* As = sm;                  // [2][128*GP]
    float* Bs = sm + 2 * 128 * GP;   // [2][128*GP]

    const int tid = threadIdx.x;
    const int wid = tid >> 5, lane = tid & 31;
    const int g = lane >> 2, tig = lane & 3;
    const int wm = (wid >> 1) * 32, wn = (wid & 1) * 64;
    const int n0 = blockIdx.x * 128;
    const int m0 = blockIdx.y * 128;
    const int c4 = tid & 7;          // float4 col index within 32-float chunk row

    float4 ar[4], br[4];
    float acc[2][8][4];
#pragma unroll
    for (int mi = 0; mi < 2; mi++)
#pragma unroll
        for (int ni = 0; ni < 8; ni++)
#pragma unroll
            for (int e = 0; e < 4; e++) acc[mi][ni][e] = 0.f;

#define LOADG(c) {                                                              \
    const float* Ap = x + (size_t)m0 * DIM + (c) * 32;                          \
    const float* Bp = w + (size_t)n0 * DIM + (c) * 32;                          \
    _Pragma("unroll")                                                           \
    for (int it = 0; it < 4; it++) {                                            \
        int r = (it * 256 + tid) >> 3;                                          \
        ar[it] = *(const float4*)(Ap + (size_t)r * DIM + c4 * 4);               \
        br[it] = *(const float4*)(Bp + (size_t)r * DIM + c4 * 4);               \
    } }

#define STORES(buf) {                                                           \
    float* ab = As + (buf) * 128 * GP;                                          \
    float* bb = Bs + (buf) * 128 * GP;                                          \
    _Pragma("unroll")                                                           \
    for (int it = 0; it < 4; it++) {                                            \
        int r = (it * 256 + tid) >> 3;                                          \
        float av[4] = {ar[it].x, ar[it].y, ar[it].z, ar[it].w};                 \
        float bv[4] = {br[it].x, br[it].y, br[it].z, br[it].w};                 \
        _Pragma("unroll")                                                       \
        for (int e = 0; e < 4; e++) {                                           \
            int p = perm8(c4 * 4 + e);                                          \
            ab[r * GP + p] = __uint_as_float(f2tf32(av[e]));                    \
            bb[r * GP + p] = __uint_as_float(f2tf32(bv[e]));                    \
        }                                                                       \
    } }

    LOADG(0);
    STORES(0);
    __syncthreads();

    int cur = 0;
    for (int c = 0; c < DIM / 32; c++) {
        if (c < DIM / 32 - 1) LOADG(c + 1);
        const float* ab = As + cur * 128 * GP;
        const float* bb = Bs + cur * 128 * GP;
#pragma unroll
        for (int s = 0; s < 4; s++) {
            float2 alo[2], ahi[2];
#pragma unroll
            for (int mi = 0; mi < 2; mi++) {
                int r0 = wm + mi * 16 + g;
                alo[mi] = *(const float2*)&ab[r0 * GP + s * 8 + tig * 2];
                ahi[mi] = *(const float2*)&ab[(r0 + 8) * GP + s * 8 + tig * 2];
            }
#pragma unroll
            for (int ni = 0; ni < 8; ni++) {
                float2 bf = *(const float2*)&bb[(wn + ni * 8 + g) * GP + s * 8 + tig * 2];
#pragma unroll
                for (int mi = 0; mi < 2; mi++) {
                    mma8(acc[mi][ni],
                         __float_as_uint(alo[mi].x), __float_as_uint(ahi[mi].x),
                         __float_as_uint(alo[mi].y), __float_as_uint(ahi[mi].y),
                         __float_as_uint(bf.x), __float_as_uint(bf.y));
                }
            }
        }
        if (c < DIM / 32 - 1) STORES(cur ^ 1);
        __syncthreads();
        cur ^= 1;
    }

    // Epilogue: bias + scale, round to tf32, scatter to g_q/g_k/g_v.
    const int nb = n0 + wn;                 // 64-aligned -> single (seg, head)
    const int seg = nb >> 10;
    const int h = (nb & 1023) >> 6;
    float* dst = (seg == 0) ? g_q : (seg == 1) ? g_k : g_v;
    const float sc = (seg == 0) ? SCALE : 1.0f;

#pragma unroll
    for (int mi = 0; mi < 2; mi++) {
        int r0 = m0 + wm + mi * 16 + g;     // and r0+8
        int bb0 = r0 >> 11;                  // /2048
        int nrow = r0 & 2047;
        float* d0 = dst + ((size_t)(bb0 * NH + h) * Nseq + nrow) * HD;
        float* d1 = d0 + 8 * HD;             // row r0+8 (same batch)
#pragma unroll
        for (int ni = 0; ni < 8; ni++) {
            int dcol = ni * 8 + 2 * tig;
            float b0 = bias[nb + dcol], b1 = bias[nb + dcol + 1];
            float2 v0, v1;
            v0.x = __uint_as_float(f2tf32((acc[mi][ni][0] + b0) * sc));
            v0.y = __uint_as_float(f2tf32((acc[mi][ni][1] + b1) * sc));
            v1.x = __uint_as_float(f2tf32((acc[mi][ni][2] + b0) * sc));
            v1.y = __uint_as_float(f2tf32((acc[mi][ni][3] + b1) * sc));
            *(float2*)&d0[dcol] = v0;
            *(float2*)&d1[dcol] = v1;
        }
    }
}

// ---------------------------------------------------------------------------
// Flash attention, tf32 mma: CTA = 128 queries x 64-key tiles, 8 warps,
// each warp owns 16 full rows (warp-local softmax).
// ---------------------------------------------------------------------------
#define AP 68                        // smem row pitch
#define QS_OFF 0
#define KS_OFF (128 * AP)
#define VS_OFF (KS_OFF + 64 * AP)
#define PS_OFF (VS_OFF + 64 * AP)
#define ATTN_SMEM ((PS_OFF + 128 * AP) * 4)   // 104448 B

__global__ __launch_bounds__(256) void attn_mma(float* __restrict__ out) {
    extern __shared__ float sm[];
    float* Qs = sm + QS_OFF;   // [128][AP], perm over d
    float* Ks = sm + KS_OFF;   // [64][AP],  perm over d
    float* Vs = sm + VS_OFF;   // [64(d)][AP], transposed, perm over key
    float* Ps = sm + PS_OFF;   // [128][AP], plain

    const int bh = blockIdx.x;
    const int q0 = blockIdx.y * 128;
    const float* Qg = g_q + (size_t)bh * Nseq * HD;
    const float* Kg = g_k + (size_t)bh * Nseq * HD;
    const float* Vg = g_v + (size_t)bh * Nseq * HD;

    const int tid = threadIdx.x;
    const int wid = tid >> 5, lane = tid & 31;
    const int g = lane >> 2, tig = lane & 3;
    const int r0 = wid * 16 + g;           // warp-owned rows r0, r0+8

    // Load Q tile (perm over d). Values are already tf32-rounded.
    for (int i = tid; i < 128 * 64; i += 256) {
        int r = i >> 6, d = i & 63;
        Qs[r * AP + perm8(d)] = Qg[(size_t)(q0 + r) * HD + d];
    }

    float o[8][4];
#pragma unroll
    for (int ni = 0; ni < 8; ni++)
#pragma unroll
        for (int e = 0; e < 4; e++) o[ni][e] = 0.f;
    float m0r = -INFINITY, m1r = -INFINITY, l0 = 0.f, l1 = 0.f;

    for (int t = 0; t < Nseq; t += 64) {
        // Load K (perm over d) and V (transposed, perm over key).
        for (int i = tid; i < 64 * 64; i += 256) {
            int r = i >> 6, d = i & 63;
            float kv = Kg[(size_t)(t + r) * HD + d];
            float vv = Vg[(size_t)(t + r) * HD + d];
            Ks[r * AP + perm8(d)] = kv;
            Vs[d * AP + perm8(r)] = vv;
        }
        __syncthreads();

        // S = Q K^T
        float sfr[8][4];
#pragma unroll
        for (int ni = 0; ni < 8; ni++)
#pragma unroll
            for (int e = 0; e < 4; e++) sfr[ni][e] = 0.f;
#pragma unroll
        for (int s = 0; s < 8; s++) {
            float2 qlo = *(const float2*)&Qs[r0 * AP + s * 8 + tig * 2];
            float2 qhi = *(const float2*)&Qs[(r0 + 8) * AP + s * 8 + tig * 2];
#pragma unroll
            for (int ni = 0; ni < 8; ni++) {
                float2 kb = *(const float2*)&Ks[(ni * 8 + g) * AP + s * 8 + tig * 2];
                mma8(sfr[ni],
                     __float_as_uint(qlo.x), __float_as_uint(qhi.x),
                     __float_as_uint(qlo.y), __float_as_uint(qhi.y),
                     __float_as_uint(kb.x), __float_as_uint(kb.y));
            }
        }

        // Online softmax (rows r0 and r0+8; reduce across the 4 tig lanes).
        float mx0 = -INFINITY, mx1 = -INFINITY;
#pragma unroll
        for (int ni = 0; ni < 8; ni++) {
            mx0 = fmaxf(mx0, fmaxf(sfr[ni][0], sfr[ni][1]));
            mx1 = fmaxf(mx1, fmaxf(sfr[ni][2], sfr[ni][3]));
        }
        mx0 = fmaxf(mx0, __shfl_xor_sync(0xffffffffu, mx0, 1));
        mx0 = fmaxf(mx0, __shfl_xor_sync(0xffffffffu, mx0, 2));
        mx1 = fmaxf(mx1, __shfl_xor_sync(0xffffffffu, mx1, 1));
        mx1 = fmaxf(mx1, __shfl_xor_sync(0xffffffffu, mx1, 2));
        float nm0 = fmaxf(m0r, mx0), nm1 = fmaxf(m1r, mx1);
        float al0 = __expf(m0r - nm0), al1 = __expf(m1r - nm1);
        m0r = nm0; m1r = nm1;
        float rs0 = 0.f, rs1 = 0.f;
#pragma unroll
        for (int ni = 0; ni < 8; ni++) {
            sfr[ni][0] = __expf(sfr[ni][0] - nm0);
            sfr[ni][1] = __expf(sfr[ni][1] - nm0);
            sfr[ni][2] = __expf(sfr[ni][2] - nm1);
            sfr[ni][3] = __expf(sfr[ni][3] - nm1);
            rs0 += sfr[ni][0] + sfr[ni][1];
            rs1 += sfr[ni][2] + sfr[ni][3];
        }
        rs0 += __shfl_xor_sync(0xffffffffu, rs0, 1);
        rs0 += __shfl_xor_sync(0xffffffffu, rs0, 2);
        rs1 += __shfl_xor_sync(0xffffffffu, rs1, 1);
        rs1 += __shfl_xor_sync(0xffffffffu, rs1, 2);
        l0 = l0 * al0 + rs0;
        l1 = l1 * al1 + rs1;
#pragma unroll
        for (int ni = 0; ni < 8; ni++) {
            o[ni][0] *= al0; o[ni][1] *= al0;
            o[ni][2] *= al1; o[ni][3] *= al1;
        }

        // Store P (tf32-rounded) — warp-local region, no CTA barrier needed.
#pragma unroll
        for (int ni = 0; ni < 8; ni++) {
            float2 p0, p1;
            p0.x = __uint_as_float(f2tf32(sfr[ni][0]));
            p0.y = __uint_as_float(f2tf32(sfr[ni][1]));
            p1.x = __uint_as_float(f2tf32(sfr[ni][2]));
            p1.y = __uint_as_float(f2tf32(sfr[ni][3]));
            *(float2*)&Ps[r0 * AP + ni * 8 + 2 * tig] = p0;
            *(float2*)&Ps[(r0 + 8) * AP + ni * 8 + 2 * tig] = p1;
        }
        __syncwarp();

        // O += P V
        const uint32_t* Pu = (const uint32_t*)Ps;
#pragma unroll
        for (int s = 0; s < 8; s++) {
            uint32_t a0 = Pu[r0 * AP + s * 8 + tig];
            uint32_t a1 = Pu[(r0 + 8) * AP + s * 8 + tig];
            uint32_t a2 = Pu[r0 * AP + s * 8 + tig + 4];
            uint32_t a3 = Pu[(r0 + 8) * AP + s * 8 + tig + 4];
#pragma unroll
            for (int ni = 0; ni < 8; ni++) {
                float2 vb = *(const float2*)&Vs[(ni * 8 + g) * AP + s * 8 + tig * 2];
                mma8(o[ni], a0, a1, a2, a3,
                     __float_as_uint(vb.x), __float_as_uint(vb.y));
            }
        }
        __syncthreads();
    }

    // Final write: out[b, q, h*64 + d]
    const int bb = bh >> 4;
    const int h = bh & 15;
    float inv0 = 1.0f / l0, inv1 = 1.0f / l1;
    float* p0 = out + ((size_t)(bb * Nseq + q0 + r0)) * DIM + h * HD;
    float* p1 = out + ((size_t)(bb * Nseq + q0 + r0 + 8)) * DIM + h * HD;
#pragma unroll
    for (int ni = 0; ni < 8; ni++) {
        int d = ni * 8 + 2 * tig;
        float2 v0 = make_float2(o[ni][0] * inv0, o[ni][1] * inv0);
        float2 v1 = make_float2(o[ni][2] * inv1, o[ni][3] * inv1);
        *(float2*)&p0[d] = v0;
        *(float2*)&p1[d] = v1;
    }
}

extern "C" void kernel_launch(void* const* d_in, const int* in_sizes, int n_in,
                              void* d_out, int out_size) {
    const float* x = (const float*)d_in[0];
    const float* w = (const float*)d_in[1];
    const float* bias = (const float*)d_in[2];
    float* out = (float*)d_out;

    cudaFuncSetAttribute(qkv_gemm_mma,
                         cudaFuncAttributeMaxDynamicSharedMemorySize, GEMM_SMEM);
    cudaFuncSetAttribute(attn_mma,
                         cudaFuncAttributeMaxDynamicSharedMemorySize, ATTN_SMEM);

    dim3 ggrid(3 * DIM / 128, Bdim * Nseq / 128);  // (24, 64)
    qkv_gemm_mma<<<ggrid, 256, GEMM_SMEM>>>(x, w, bias);

    dim3 agrid(Bdim * NH, Nseq / 128);             // (64, 16)
    attn_mma<<<agrid, 256, ATTN_SMEM>>>(out);
}